// round 5
// baseline (speedup 1.0000x reference)
#include <cuda_runtime.h>
#include <math.h>

#define N_NODES 50000
#define N_EDGES 800000
#define TOT_E   (N_EDGES + N_NODES)
#define IN_CH   128
#define HEADS   4
#define OUT_CH  64
#define HC      256
#define NEG_SLOPE 0.2f
#define SCAN_BLOCKS ((N_NODES + 1023) / 1024)   // 49

// ---- scratch (device globals; no allocation allowed) ----
__device__ float g_xl  [N_NODES * HC];      // projected features (51.2MB, L2-resident)
__device__ float g_asrc[N_NODES * HEADS];
__device__ float g_adst[N_NODES * HEADS];
__device__ float g_den [N_NODES * HEADS];   // softmax denominators
__device__ int   g_deg [N_NODES];
__device__ int   g_rank[TOT_E];             // rank of edge within its dst segment
__device__ int   g_incl[N_NODES];
__device__ int   g_bsum[SCAN_BLOCKS];
__device__ int   g_boff[SCAN_BLOCKS];
__device__ int   g_ptr [N_NODES + 1];       // CSR row ptr (by dst)
__device__ int   g_ssrc[TOT_E];             // dst-sorted: src node per slot
__device__ float g_sexp[TOT_E * HEADS];     // dst-sorted: exp(alpha) per slot (13.6MB)

__device__ __forceinline__ float lrelu(float a) { return a > 0.f ? a : NEG_SLOPE * a; }

__device__ __forceinline__ void red4(float* p, float a, float b, float c, float d) {
    asm volatile("red.global.add.v4.f32 [%0], {%1, %2, %3, %4};"
                 :: "l"(p), "f"(a), "f"(b), "f"(c), "f"(d) : "memory");
}
__device__ __forceinline__ void fma2(unsigned long long& acc,
                                     unsigned long long a, unsigned long long b) {
    asm("fma.rn.f32x2 %0, %1, %2, %0;" : "+l"(acc) : "l"(a), "l"(b));
}
__device__ __forceinline__ float f2lo(unsigned long long v) {
    return __uint_as_float((unsigned)(v & 0xFFFFFFFFull));
}
__device__ __forceinline__ float f2hi(unsigned long long v) {
    return __uint_as_float((unsigned)(v >> 32));
}

// ---------------- K0: zero deg + den ----------------
__global__ void k_init() {
    int i = blockIdx.x * blockDim.x + threadIdx.x;
    if (i < N_NODES) {
        g_deg[i] = 0;
        ((float4*)g_den)[i] = make_float4(0.f, 0.f, 0.f, 0.f);
    }
}

// ------- K1: xl = x @ W^T via fma.rn.f32x2, fused attention logits ------
__global__ void __launch_bounds__(256) k_gemm(const float* __restrict__ x,
                                              const float* __restrict__ W,
                                              const float* __restrict__ att_src,
                                              const float* __restrict__ att_dst) {
    __shared__ __align__(16) float xs[16 * IN_CH];   // 8KB
    __shared__ float red_s[8][16];
    __shared__ float red_d[8][16];
    const int n0 = blockIdx.x * 16;           // 50000 = 3125 * 16
    const int t  = threadIdx.x;               // output channel 0..255
    const int wid  = t >> 5;
    const int lane = t & 31;

    const float* xsrc = x + (size_t)n0 * IN_CH;
    #pragma unroll
    for (int i = t; i < 16 * IN_CH; i += 256) xs[i] = xsrc[i];
    __syncthreads();

    // packed accumulators: (even-k partial, odd-k partial)
    unsigned long long acc2[16];
    #pragma unroll
    for (int n = 0; n < 16; n++) acc2[n] = 0ull;

    const ulonglong2* Wr = (const ulonglong2*)(W + (size_t)t * IN_CH);
    #pragma unroll 4
    for (int kt = 0; kt < IN_CH / 4; kt++) {       // 4 k's per iter
        ulonglong2 w = Wr[kt];                     // pairs (k,k+1),(k+2,k+3)
        #pragma unroll
        for (int n = 0; n < 16; n++) {
            ulonglong2 xv = *(const ulonglong2*)&xs[n * IN_CH + kt * 4]; // LDS.128
            fma2(acc2[n], w.x, xv.x);
            fma2(acc2[n], w.y, xv.y);
        }
    }

    float acc[16];
    #pragma unroll
    for (int n = 0; n < 16; n++) acc[n] = f2lo(acc2[n]) + f2hi(acc2[n]);

    #pragma unroll
    for (int n = 0; n < 16; n++)
        g_xl[(size_t)(n0 + n) * HC + t] = acc[n];

    // fused logits: reduce acc[n]*att over the 64 channels of head t>>6
    float as_t = att_src[t];
    float ad_t = att_dst[t];
    float ps[16], pd[16];
    #pragma unroll
    for (int n = 0; n < 16; n++) { ps[n] = acc[n] * as_t; pd[n] = acc[n] * ad_t; }
    #pragma unroll
    for (int off = 16; off; off >>= 1) {
        #pragma unroll
        for (int n = 0; n < 16; n++) {
            ps[n] += __shfl_xor_sync(0xFFFFFFFFu, ps[n], off);
            pd[n] += __shfl_xor_sync(0xFFFFFFFFu, pd[n], off);
        }
    }
    if (lane == 0) {
        #pragma unroll
        for (int n = 0; n < 16; n++) { red_s[wid][n] = ps[n]; red_d[wid][n] = pd[n]; }
    }
    __syncthreads();
    if (t < 64) {                             // head h spans warps 2h, 2h+1
        int h = t >> 4, n = t & 15;
        g_asrc[(size_t)(n0 + n) * 4 + h] = red_s[2 * h][n] + red_s[2 * h + 1][n];
    } else if (t < 128) {
        int u = t - 64, h = u >> 4, n = u & 15;
        g_adst[(size_t)(n0 + n) * 4 + h] = red_d[2 * h][n] + red_d[2 * h + 1][n];
    }
}

// ------- K2: dst-degree histogram + per-edge rank ----------------
__global__ void k_hist(const int* __restrict__ ei) {
    int e = blockIdx.x * blockDim.x + threadIdx.x;
    if (e >= TOT_E) return;
    int d = (e < N_EDGES) ? ei[N_EDGES + e] : (e - N_EDGES);
    g_rank[e] = atomicAdd(&g_deg[d], 1);
}

// ---------------- K3a/b/c: prefix scan -> CSR ptr ----------------
__global__ void __launch_bounds__(1024) k_scanA() {
    __shared__ int s[1024];
    int i = blockIdx.x * 1024 + threadIdx.x;
    int v = (i < N_NODES) ? g_deg[i] : 0;
    s[threadIdx.x] = v;
    __syncthreads();
    #pragma unroll
    for (int off = 1; off < 1024; off <<= 1) {
        int u = (threadIdx.x >= off) ? s[threadIdx.x - off] : 0;
        __syncthreads();
        s[threadIdx.x] += u;
        __syncthreads();
    }
    if (i < N_NODES) g_incl[i] = s[threadIdx.x];
    if (threadIdx.x == 1023) g_bsum[blockIdx.x] = s[1023];
}
__global__ void k_scanB() {
    if (threadIdx.x == 0) {
        int run = 0;
        for (int b = 0; b < SCAN_BLOCKS; b++) { g_boff[b] = run; run += g_bsum[b]; }
    }
}
__global__ void __launch_bounds__(1024) k_scanC() {
    int i = blockIdx.x * 1024 + threadIdx.x;
    if (i >= N_NODES) return;
    int incl = g_incl[i] + g_boff[blockIdx.x];
    g_ptr[i] = incl - g_deg[i];
    if (i == N_NODES - 1) g_ptr[N_NODES] = incl;
}

// ------- K4: fill (no atomics) + exp + denominators -------
__global__ void k_fill(const int* __restrict__ ei) {
    int e = blockIdx.x * blockDim.x + threadIdx.x;
    if (e >= TOT_E) return;
    int s, d;
    if (e < N_EDGES) { s = ei[e]; d = ei[N_EDGES + e]; }
    else             { s = d = e - N_EDGES; }
    int pos = g_ptr[d] + g_rank[e];
    float4 as = *(const float4*)&g_asrc[(size_t)s * 4];
    float4 ad = *(const float4*)&g_adst[(size_t)d * 4];
    float4 ex;
    ex.x = expf(lrelu(as.x + ad.x));
    ex.y = expf(lrelu(as.y + ad.y));
    ex.z = expf(lrelu(as.z + ad.z));
    ex.w = expf(lrelu(as.w + ad.w));
    g_ssrc[pos] = s;
    *(float4*)&g_sexp[(size_t)pos * 4] = ex;
    red4(&g_den[(size_t)d * 4], ex.x, ex.y, ex.z, ex.w);
}

// ------- K5: gather-aggregate, warp per node, 4-way unroll -------
__global__ void __launch_bounds__(256) k_agg(const float* __restrict__ bias,
                                             float* __restrict__ out) {
    int w    = (blockIdx.x * blockDim.x + threadIdx.x) >> 5;   // node id
    int lane = threadIdx.x & 31;
    if (w >= N_NODES) return;
    const int d  = w;
    const int p0 = g_ptr[d];
    const int p1 = g_ptr[d + 1];

    float4 den = *(const float4*)&g_den[(size_t)d * 4];
    float4 idn = make_float4(1.f / den.x, 1.f / den.y, 1.f / den.z, 1.f / den.w);
    const bool lo = (lane < 16);   // lane -> float4 idx {lane, lane+32} -> heads {lane>>4, 2+(lane>>4)}

    float4 a0 = make_float4(0.f, 0.f, 0.f, 0.f);
    float4 a1 = make_float4(0.f, 0.f, 0.f, 0.f);

    int p = p0;
    for (; p + 4 <= p1; p += 4) {             // 4-way unroll: 8 gathers in flight
        int s0 = g_ssrc[p];
        int s1 = g_ssrc[p + 1];
        int s2 = g_ssrc[p + 2];
        int s3 = g_ssrc[p + 3];
        const float4* x0 = (const float4*)&g_xl[(size_t)s0 * HC];
        const float4* x1 = (const float4*)&g_xl[(size_t)s1 * HC];
        const float4* x2 = (const float4*)&g_xl[(size_t)s2 * HC];
        const float4* x3 = (const float4*)&g_xl[(size_t)s3 * HC];
        float4 vA0 = x0[lane], vA1 = x0[lane + 32];
        float4 vB0 = x1[lane], vB1 = x1[lane + 32];
        float4 vC0 = x2[lane], vC1 = x2[lane + 32];
        float4 vD0 = x3[lane], vD1 = x3[lane + 32];
        float4 eA = *(const float4*)&g_sexp[(size_t)p * 4];
        float4 eB = *(const float4*)&g_sexp[(size_t)(p + 1) * 4];
        float4 eC = *(const float4*)&g_sexp[(size_t)(p + 2) * 4];
        float4 eD = *(const float4*)&g_sexp[(size_t)(p + 3) * 4];
        float cA0 = lo ? eA.x * idn.x : eA.y * idn.y;
        float cA1 = lo ? eA.z * idn.z : eA.w * idn.w;
        float cB0 = lo ? eB.x * idn.x : eB.y * idn.y;
        float cB1 = lo ? eB.z * idn.z : eB.w * idn.w;
        float cC0 = lo ? eC.x * idn.x : eC.y * idn.y;
        float cC1 = lo ? eC.z * idn.z : eC.w * idn.w;
        float cD0 = lo ? eD.x * idn.x : eD.y * idn.y;
        float cD1 = lo ? eD.z * idn.z : eD.w * idn.w;
        a0.x += cA0 * vA0.x; a0.y += cA0 * vA0.y; a0.z += cA0 * vA0.z; a0.w += cA0 * vA0.w;
        a1.x += cA1 * vA1.x; a1.y += cA1 * vA1.y; a1.z += cA1 * vA1.z; a1.w += cA1 * vA1.w;
        a0.x += cB0 * vB0.x; a0.y += cB0 * vB0.y; a0.z += cB0 * vB0.z; a0.w += cB0 * vB0.w;
        a1.x += cB1 * vB1.x; a1.y += cB1 * vB1.y; a1.z += cB1 * vB1.z; a1.w += cB1 * vB1.w;
        a0.x += cC0 * vC0.x; a0.y += cC0 * vC0.y; a0.z += cC0 * vC0.z; a0.w += cC0 * vC0.w;
        a1.x += cC1 * vC1.x; a1.y += cC1 * vC1.y; a1.z += cC1 * vC1.z; a1.w += cC1 * vC1.w;
        a0.x += cD0 * vD0.x; a0.y += cD0 * vD0.y; a0.z += cD0 * vD0.z; a0.w += cD0 * vD0.w;
        a1.x += cD1 * vD1.x; a1.y += cD1 * vD1.y; a1.z += cD1 * vD1.z; a1.w += cD1 * vD1.w;
    }
    for (; p < p1; p++) {
        int    s  = g_ssrc[p];
        float4 ex = *(const float4*)&g_sexp[(size_t)p * 4];
        const float4* xp = (const float4*)&g_xl[(size_t)s * HC];
        float4 v0 = xp[lane], v1 = xp[lane + 32];
        float c0 = lo ? ex.x * idn.x : ex.y * idn.y;
        float c1 = lo ? ex.z * idn.z : ex.w * idn.w;
        a0.x += c0 * v0.x; a0.y += c0 * v0.y; a0.z += c0 * v0.z; a0.w += c0 * v0.w;
        a1.x += c1 * v1.x; a1.y += c1 * v1.y; a1.z += c1 * v1.z; a1.w += c1 * v1.w;
    }

    float4 b0 = ((const float4*)bias)[lane];
    float4 b1 = ((const float4*)bias)[lane + 32];
    a0.x += b0.x; a0.y += b0.y; a0.z += b0.z; a0.w += b0.w;
    a1.x += b1.x; a1.y += b1.y; a1.z += b1.z; a1.w += b1.w;
    a0.x = a0.x > 0.f ? a0.x : expm1f(a0.x);
    a0.y = a0.y > 0.f ? a0.y : expm1f(a0.y);
    a0.z = a0.z > 0.f ? a0.z : expm1f(a0.z);
    a0.w = a0.w > 0.f ? a0.w : expm1f(a0.w);
    a1.x = a1.x > 0.f ? a1.x : expm1f(a1.x);
    a1.y = a1.y > 0.f ? a1.y : expm1f(a1.y);
    a1.z = a1.z > 0.f ? a1.z : expm1f(a1.z);
    a1.w = a1.w > 0.f ? a1.w : expm1f(a1.w);

    float4* op = (float4*)(out + (size_t)d * HC);
    op[lane]      = a0;
    op[lane + 32] = a1;
}

extern "C" void kernel_launch(void* const* d_in, const int* in_sizes, int n_in,
                              void* d_out, int out_size) {
    const float* x    = (const float*)d_in[0];
    const int*   ei   = (const int*)d_in[1];    // int32 (JAX x64 disabled)
    const float* W    = (const float*)d_in[2];
    const float* asrc = (const float*)d_in[3];
    const float* adst = (const float*)d_in[4];
    const float* bias = (const float*)d_in[5];
    float* out = (float*)d_out;

    (void)in_sizes; (void)n_in; (void)out_size;

    k_init<<<(N_NODES + 255) / 256, 256>>>();
    k_gemm<<<N_NODES / 16, 256>>>(x, W, asrc, adst);
    k_hist<<<(TOT_E + 255) / 256, 256>>>(ei);
    k_scanA<<<SCAN_BLOCKS, 1024>>>();
    k_scanB<<<1, 32>>>();
    k_scanC<<<SCAN_BLOCKS, 1024>>>();
    k_fill<<<(TOT_E + 255) / 256, 256>>>(ei);
    k_agg<<<(N_NODES * 32 + 255) / 256, 256>>>(bias, out);
}

// round 6
// speedup vs baseline: 1.0012x; 1.0012x over previous
#include <cuda_runtime.h>
#include <math.h>

#define N_NODES 50000
#define N_EDGES 800000
#define TOT_E   (N_EDGES + N_NODES)
#define IN_CH   128
#define HEADS   4
#define OUT_CH  64
#define HC      256
#define NEG_SLOPE 0.2f
#define SCAN_BLOCKS ((N_NODES + 1023) / 1024)   // 49

// ---- scratch (device globals; no allocation allowed) ----
__device__ float g_xl  [N_NODES * HC];      // projected features (51.2MB, L2-resident)
__device__ float g_asrc[N_NODES * HEADS];
__device__ float g_adst[N_NODES * HEADS];
__device__ int   g_deg [N_NODES];
__device__ int   g_rank[TOT_E];             // rank of edge within its dst segment
__device__ int   g_incl[N_NODES];
__device__ int   g_bsum[SCAN_BLOCKS];
__device__ int   g_boff[SCAN_BLOCKS];
__device__ int   g_ptr [N_NODES + 1];       // CSR row ptr (by dst)
__device__ int   g_ssrc[TOT_E];             // dst-sorted: src node per slot
__device__ float g_sexp[TOT_E * HEADS];     // dst-sorted: exp(alpha) per slot (13.6MB)

__device__ __forceinline__ float lrelu(float a) { return a > 0.f ? a : NEG_SLOPE * a; }

__device__ __forceinline__ void fma2(unsigned long long& acc,
                                     unsigned long long a, unsigned long long b) {
    asm("fma.rn.f32x2 %0, %1, %2, %0;" : "+l"(acc) : "l"(a), "l"(b));
}
__device__ __forceinline__ float f2lo(unsigned long long v) {
    return __uint_as_float((unsigned)(v & 0xFFFFFFFFull));
}
__device__ __forceinline__ float f2hi(unsigned long long v) {
    return __uint_as_float((unsigned)(v >> 32));
}

// ---------------- K0: zero deg ----------------
__global__ void k_init() {
    int i = blockIdx.x * blockDim.x + threadIdx.x;
    if (i < N_NODES) g_deg[i] = 0;
}

// ------- K1: dst-degree histogram + per-edge rank ----------------
__global__ void k_hist(const int* __restrict__ ei) {
    int e = blockIdx.x * blockDim.x + threadIdx.x;
    if (e >= TOT_E) return;
    int d = (e < N_EDGES) ? ei[N_EDGES + e] : (e - N_EDGES);
    g_rank[e] = atomicAdd(&g_deg[d], 1);
}

// ---------------- K2a/b/c: prefix scan -> CSR ptr ----------------
__global__ void __launch_bounds__(1024) k_scanA() {
    __shared__ int s[1024];
    int i = blockIdx.x * 1024 + threadIdx.x;
    int v = (i < N_NODES) ? g_deg[i] : 0;
    s[threadIdx.x] = v;
    __syncthreads();
    #pragma unroll
    for (int off = 1; off < 1024; off <<= 1) {
        int u = (threadIdx.x >= off) ? s[threadIdx.x - off] : 0;
        __syncthreads();
        s[threadIdx.x] += u;
        __syncthreads();
    }
    if (i < N_NODES) g_incl[i] = s[threadIdx.x];
    if (threadIdx.x == 1023) g_bsum[blockIdx.x] = s[1023];
}
__global__ void k_scanB() {
    if (threadIdx.x == 0) {
        int run = 0;
        for (int b = 0; b < SCAN_BLOCKS; b++) { g_boff[b] = run; run += g_bsum[b]; }
    }
}
__global__ void __launch_bounds__(1024) k_scanC() {
    int i = blockIdx.x * 1024 + threadIdx.x;
    if (i >= N_NODES) return;
    int incl = g_incl[i] + g_boff[blockIdx.x];
    g_ptr[i] = incl - g_deg[i];
    if (i == N_NODES - 1) g_ptr[N_NODES] = incl;
}

// ------- K3: xl = x @ W^T via fma.rn.f32x2, fused attention logits ------
// (launched at profiled index 3)
__global__ void __launch_bounds__(256) k_gemm(const float* __restrict__ x,
                                              const float* __restrict__ W,
                                              const float* __restrict__ att_src,
                                              const float* __restrict__ att_dst) {
    __shared__ __align__(16) float xs[16 * IN_CH];   // 8KB
    __shared__ float red_s[8][16];
    __shared__ float red_d[8][16];
    const int n0 = blockIdx.x * 16;           // 50000 = 3125 * 16
    const int t  = threadIdx.x;               // output channel 0..255
    const int wid  = t >> 5;
    const int lane = t & 31;

    const float* xsrc = x + (size_t)n0 * IN_CH;
    #pragma unroll
    for (int i = t; i < 16 * IN_CH; i += 256) xs[i] = xsrc[i];
    __syncthreads();

    // packed accumulators: (even-k partial, odd-k partial)
    unsigned long long acc2[16];
    #pragma unroll
    for (int n = 0; n < 16; n++) acc2[n] = 0ull;

    const ulonglong2* Wr = (const ulonglong2*)(W + (size_t)t * IN_CH);
    #pragma unroll 4
    for (int kt = 0; kt < IN_CH / 4; kt++) {       // 4 k's per iter
        ulonglong2 w = Wr[kt];                     // pairs (k,k+1),(k+2,k+3)
        #pragma unroll
        for (int n = 0; n < 16; n++) {
            ulonglong2 xv = *(const ulonglong2*)&xs[n * IN_CH + kt * 4]; // broadcast LDS.128
            fma2(acc2[n], w.x, xv.x);
            fma2(acc2[n], w.y, xv.y);
        }
    }

    float acc[16];
    #pragma unroll
    for (int n = 0; n < 16; n++) acc[n] = f2lo(acc2[n]) + f2hi(acc2[n]);

    #pragma unroll
    for (int n = 0; n < 16; n++)
        g_xl[(size_t)(n0 + n) * HC + t] = acc[n];

    // fused logits: reduce acc[n]*att over the 64 channels of head t>>6
    float as_t = att_src[t];
    float ad_t = att_dst[t];
    float ps[16], pd[16];
    #pragma unroll
    for (int n = 0; n < 16; n++) { ps[n] = acc[n] * as_t; pd[n] = acc[n] * ad_t; }
    #pragma unroll
    for (int off = 16; off; off >>= 1) {
        #pragma unroll
        for (int n = 0; n < 16; n++) {
            ps[n] += __shfl_xor_sync(0xFFFFFFFFu, ps[n], off);
            pd[n] += __shfl_xor_sync(0xFFFFFFFFu, pd[n], off);
        }
    }
    if (lane == 0) {
        #pragma unroll
        for (int n = 0; n < 16; n++) { red_s[wid][n] = ps[n]; red_d[wid][n] = pd[n]; }
    }
    __syncthreads();
    if (t < 64) {                             // head h spans warps 2h, 2h+1
        int h = t >> 4, n = t & 15;
        g_asrc[(size_t)(n0 + n) * 4 + h] = red_s[2 * h][n] + red_s[2 * h + 1][n];
    } else if (t < 128) {
        int u = t - 64, h = u >> 4, n = u & 15;
        g_adst[(size_t)(n0 + n) * 4 + h] = red_d[2 * h][n] + red_d[2 * h + 1][n];
    }
}

// ------- K4: fill sorted (src, exp) — no atomics, no den -------
__global__ void k_fill(const int* __restrict__ ei) {
    int e = blockIdx.x * blockDim.x + threadIdx.x;
    if (e >= TOT_E) return;
    int s, d;
    if (e < N_EDGES) { s = ei[e]; d = ei[N_EDGES + e]; }
    else             { s = d = e - N_EDGES; }
    int pos = g_ptr[d] + g_rank[e];
    float4 as = *(const float4*)&g_asrc[(size_t)s * 4];
    float4 ad = *(const float4*)&g_adst[(size_t)d * 4];
    float4 ex;
    ex.x = expf(lrelu(as.x + ad.x));
    ex.y = expf(lrelu(as.y + ad.y));
    ex.z = expf(lrelu(as.z + ad.z));
    ex.w = expf(lrelu(as.w + ad.w));
    g_ssrc[pos] = s;
    *(float4*)&g_sexp[(size_t)pos * 4] = ex;
}

// ------- K5: gather-aggregate, warp per node, in-register denominators --
__global__ void __launch_bounds__(256) k_agg(const float* __restrict__ bias,
                                             float* __restrict__ out) {
    int w    = (blockIdx.x * blockDim.x + threadIdx.x) >> 5;   // node id
    int lane = threadIdx.x & 31;
    if (w >= N_NODES) return;
    const int d  = w;
    const int p0 = g_ptr[d];
    const int p1 = g_ptr[d + 1];
    const bool lo = (lane < 16);   // lane -> f4 idx {lane, lane+32} -> heads {lane>>4, 2+(lane>>4)}

    float4 a0 = make_float4(0.f, 0.f, 0.f, 0.f);
    float4 a1 = make_float4(0.f, 0.f, 0.f, 0.f);
    float den0 = 0.f, den1 = 0.f;             // this lane's 2 head denominators

    int p = p0;
    for (; p + 4 <= p1; p += 4) {             // 4-way unroll: 8 gathers in flight
        int s0 = g_ssrc[p];
        int s1 = g_ssrc[p + 1];
        int s2 = g_ssrc[p + 2];
        int s3 = g_ssrc[p + 3];
        const float4* x0 = (const float4*)&g_xl[(size_t)s0 * HC];
        const float4* x1 = (const float4*)&g_xl[(size_t)s1 * HC];
        const float4* x2 = (const float4*)&g_xl[(size_t)s2 * HC];
        const float4* x3 = (const float4*)&g_xl[(size_t)s3 * HC];
        float4 vA0 = x0[lane], vA1 = x0[lane + 32];
        float4 vB0 = x1[lane], vB1 = x1[lane + 32];
        float4 vC0 = x2[lane], vC1 = x2[lane + 32];
        float4 vD0 = x3[lane], vD1 = x3[lane + 32];
        float4 eA = *(const float4*)&g_sexp[(size_t)p * 4];
        float4 eB = *(const float4*)&g_sexp[(size_t)(p + 1) * 4];
        float4 eC = *(const float4*)&g_sexp[(size_t)(p + 2) * 4];
        float4 eD = *(const float4*)&g_sexp[(size_t)(p + 3) * 4];
        float cA0 = lo ? eA.x : eA.y,  cA1 = lo ? eA.z : eA.w;
        float cB0 = lo ? eB.x : eB.y,  cB1 = lo ? eB.z : eB.w;
        float cC0 = lo ? eC.x : eC.y,  cC1 = lo ? eC.z : eC.w;
        float cD0 = lo ? eD.x : eD.y,  cD1 = lo ? eD.z : eD.w;
        den0 += cA0 + cB0 + cC0 + cD0;
        den1 += cA1 + cB1 + cC1 + cD1;
        a0.x += cA0 * vA0.x; a0.y += cA0 * vA0.y; a0.z += cA0 * vA0.z; a0.w += cA0 * vA0.w;
        a1.x += cA1 * vA1.x; a1.y += cA1 * vA1.y; a1.z += cA1 * vA1.z; a1.w += cA1 * vA1.w;
        a0.x += cB0 * vB0.x; a0.y += cB0 * vB0.y; a0.z += cB0 * vB0.z; a0.w += cB0 * vB0.w;
        a1.x += cB1 * vB1.x; a1.y += cB1 * vB1.y; a1.z += cB1 * vB1.z; a1.w += cB1 * vB1.w;
        a0.x += cC0 * vC0.x; a0.y += cC0 * vC0.y; a0.z += cC0 * vC0.z; a0.w += cC0 * vC0.w;
        a1.x += cC1 * vC1.x; a1.y += cC1 * vC1.y; a1.z += cC1 * vC1.z; a1.w += cC1 * vC1.w;
        a0.x += cD0 * vD0.x; a0.y += cD0 * vD0.y; a0.z += cD0 * vD0.z; a0.w += cD0 * vD0.w;
        a1.x += cD1 * vD1.x; a1.y += cD1 * vD1.y; a1.z += cD1 * vD1.z; a1.w += cD1 * vD1.w;
    }
    for (; p < p1; p++) {
        int    s  = g_ssrc[p];
        float4 ex = *(const float4*)&g_sexp[(size_t)p * 4];
        const float4* xp = (const float4*)&g_xl[(size_t)s * HC];
        float4 v0 = xp[lane], v1 = xp[lane + 32];
        float c0 = lo ? ex.x : ex.y;
        float c1 = lo ? ex.z : ex.w;
        den0 += c0; den1 += c1;
        a0.x += c0 * v0.x; a0.y += c0 * v0.y; a0.z += c0 * v0.z; a0.w += c0 * v0.w;
        a1.x += c1 * v1.x; a1.y += c1 * v1.y; a1.z += c1 * v1.z; a1.w += c1 * v1.w;
    }

    // normalize (all lanes in a 16-half computed identical den in same order)
    float i0 = 1.f / den0, i1 = 1.f / den1;
    float4 b0 = ((const float4*)bias)[lane];
    float4 b1 = ((const float4*)bias)[lane + 32];
    a0.x = a0.x * i0 + b0.x; a0.y = a0.y * i0 + b0.y;
    a0.z = a0.z * i0 + b0.z; a0.w = a0.w * i0 + b0.w;
    a1.x = a1.x * i1 + b1.x; a1.y = a1.y * i1 + b1.y;
    a1.z = a1.z * i1 + b1.z; a1.w = a1.w * i1 + b1.w;
    a0.x = a0.x > 0.f ? a0.x : expm1f(a0.x);
    a0.y = a0.y > 0.f ? a0.y : expm1f(a0.y);
    a0.z = a0.z > 0.f ? a0.z : expm1f(a0.z);
    a0.w = a0.w > 0.f ? a0.w : expm1f(a0.w);
    a1.x = a1.x > 0.f ? a1.x : expm1f(a1.x);
    a1.y = a1.y > 0.f ? a1.y : expm1f(a1.y);
    a1.z = a1.z > 0.f ? a1.z : expm1f(a1.z);
    a1.w = a1.w > 0.f ? a1.w : expm1f(a1.w);

    float4* op = (float4*)(out + (size_t)d * HC);
    op[lane]      = a0;
    op[lane + 32] = a1;
}

extern "C" void kernel_launch(void* const* d_in, const int* in_sizes, int n_in,
                              void* d_out, int out_size) {
    const float* x    = (const float*)d_in[0];
    const int*   ei   = (const int*)d_in[1];    // int32 (JAX x64 disabled)
    const float* W    = (const float*)d_in[2];
    const float* asrc = (const float*)d_in[3];
    const float* adst = (const float*)d_in[4];
    const float* bias = (const float*)d_in[5];
    float* out = (float*)d_out;

    (void)in_sizes; (void)n_in; (void)out_size;

    // order chosen so k_gemm sits at launch index 3 (the ncu-profiled slot)
    k_init<<<(N_NODES + 255) / 256, 256>>>();
    k_hist<<<(TOT_E + 255) / 256, 256>>>(ei);
    k_scanA<<<SCAN_BLOCKS, 1024>>>();
    k_gemm<<<N_NODES / 16, 256>>>(x, W, asrc, adst);
    k_scanB<<<1, 32>>>();
    k_scanC<<<SCAN_BLOCKS, 1024>>>();
    k_fill<<<(TOT_E + 255) / 256, 256>>>(ei);
    k_agg<<<(N_NODES * 32 + 255) / 256, 256>>>(bias, out);
}

// round 7
// speedup vs baseline: 1.4639x; 1.4622x over previous
#include <cuda_runtime.h>
#include <math.h>

#define N_NODES 50000
#define N_EDGES 800000
#define TOT_E   (N_EDGES + N_NODES)
#define IN_CH   128
#define HEADS   4
#define OUT_CH  64
#define HC      256
#define NEG_SLOPE 0.2f
#define SCAN_BLOCKS ((N_NODES + 1023) / 1024)   // 49
#define GEMM_TILE_N 32
#define GEMM_BLOCKS ((N_NODES + GEMM_TILE_N - 1) / GEMM_TILE_N)   // 1563

// ---- scratch (device globals; no allocation allowed) ----
__device__ float  g_xl  [N_NODES * HC];     // projected features (51.2MB, L2-resident)
__device__ float  g_asrc[N_NODES * HEADS];
__device__ float  g_adst[N_NODES * HEADS];
__device__ float2 g_Wp  [64 * HC];          // W packed: [kpair][c] = (W[c][2k], W[c][2k+1])
__device__ int    g_deg [N_NODES];
__device__ int    g_rank[TOT_E];
__device__ int    g_incl[N_NODES];
__device__ int    g_bsum[SCAN_BLOCKS];
__device__ int    g_boff[SCAN_BLOCKS];
__device__ int    g_ptr [N_NODES + 1];      // CSR row ptr (by dst)
__device__ int    g_ssrc[TOT_E];            // dst-sorted: src node per slot
__device__ float  g_sexp[TOT_E * HEADS];    // dst-sorted: exp(alpha) per slot

__device__ __forceinline__ float lrelu(float a) { return a > 0.f ? a : NEG_SLOPE * a; }

__device__ __forceinline__ void fma2(unsigned long long& acc,
                                     unsigned long long a, unsigned long long b) {
    asm("fma.rn.f32x2 %0, %1, %2, %0;" : "+l"(acc) : "l"(a), "l"(b));
}
__device__ __forceinline__ float f2lo(unsigned long long v) {
    return __uint_as_float((unsigned)(v & 0xFFFFFFFFull));
}
__device__ __forceinline__ float f2hi(unsigned long long v) {
    return __uint_as_float((unsigned)(v >> 32));
}

// ---------------- K-1: pack W into k-pair layout ----------------
__global__ void k_wpack(const float* __restrict__ W) {
    int i = blockIdx.x * blockDim.x + threadIdx.x;   // 64*256
    if (i >= 64 * HC) return;
    int kp = i >> 8, c = i & 255;
    g_Wp[kp * HC + c] = make_float2(W[(size_t)c * IN_CH + 2 * kp],
                                    W[(size_t)c * IN_CH + 2 * kp + 1]);
}

// ---------------- K0: zero deg ----------------
__global__ void k_init() {
    int i = blockIdx.x * blockDim.x + threadIdx.x;
    if (i < N_NODES) g_deg[i] = 0;
}

// ------- K1: dst-degree histogram + per-edge rank ----------------
__global__ void k_hist(const int* __restrict__ ei) {
    int e = blockIdx.x * blockDim.x + threadIdx.x;
    if (e >= TOT_E) return;
    int d = (e < N_EDGES) ? ei[N_EDGES + e] : (e - N_EDGES);
    g_rank[e] = atomicAdd(&g_deg[d], 1);
}

// ------- K2 (index 3): xl = x @ W^T, 8n x 4c per thread, fused logits ----
__global__ void __launch_bounds__(256) k_gemm(const float* __restrict__ x,
                                              const float* __restrict__ att_src,
                                              const float* __restrict__ att_dst) {
    __shared__ __align__(16) float xs[GEMM_TILE_N * IN_CH];   // 16KB
    const int n0  = blockIdx.x * GEMM_TILE_N;
    const int tid = threadIdx.x;
    const int cg  = tid & 63;       // channel group: c0 = cg*4
    const int ng  = tid >> 6;       // node group: nodes ng*8 .. ng*8+7
    const int c0  = cg * 4;

    // load x tile (clamp tail-block rows)
    for (int i = tid; i < GEMM_TILE_N * (IN_CH / 4); i += 256) {
        int node = i >> 5;                     // 32 float4 per row
        int col  = i & 31;
        int gn = n0 + node; if (gn >= N_NODES) gn = N_NODES - 1;
        *(float4*)&xs[node * IN_CH + col * 4] = ((const float4*)x)[(size_t)gn * 32 + col];
    }
    __syncthreads();

    unsigned long long acc2[8][4];
    #pragma unroll
    for (int n = 0; n < 8; n++)
        #pragma unroll
        for (int j = 0; j < 4; j++) acc2[n][j] = 0ull;

    const ulonglong2* Wp = (const ulonglong2*)g_Wp;   // [64][128] ulonglong2
    #pragma unroll 2
    for (int kp = 0; kp < 64; kp++) {
        ulonglong2 wA = Wp[kp * 128 + cg * 2];        // c0, c0+1
        ulonglong2 wB = Wp[kp * 128 + cg * 2 + 1];    // c0+2, c0+3
        #pragma unroll
        for (int n = 0; n < 8; n++) {
            unsigned long long xp =
                *(const unsigned long long*)&xs[(ng * 8 + n) * IN_CH + kp * 2]; // bcast LDS.64
            fma2(acc2[n][0], wA.x, xp);
            fma2(acc2[n][1], wA.y, xp);
            fma2(acc2[n][2], wB.x, xp);
            fma2(acc2[n][3], wB.y, xp);
        }
    }

    // finalize, store xl, compute logit partials
    float4 av = *(const float4*)&att_src[c0];
    float4 dv = *(const float4*)&att_dst[c0];
    float ps[8], pd[8];
    #pragma unroll
    for (int n = 0; n < 8; n++) {
        float4 r;
        r.x = f2lo(acc2[n][0]) + f2hi(acc2[n][0]);
        r.y = f2lo(acc2[n][1]) + f2hi(acc2[n][1]);
        r.z = f2lo(acc2[n][2]) + f2hi(acc2[n][2]);
        r.w = f2lo(acc2[n][3]) + f2hi(acc2[n][3]);
        int gn = n0 + ng * 8 + n;
        if (gn < N_NODES)
            *(float4*)&g_xl[(size_t)gn * HC + c0] = r;
        ps[n] = r.x * av.x + r.y * av.y + r.z * av.z + r.w * av.w;
        pd[n] = r.x * dv.x + r.y * dv.y + r.z * dv.z + r.w * dv.w;
    }
    // reduce over the 16 lanes sharing a head (lane = cg&31; head group = lane&16)
    #pragma unroll
    for (int off = 8; off; off >>= 1) {
        #pragma unroll
        for (int n = 0; n < 8; n++) {
            ps[n] += __shfl_xor_sync(0xFFFFFFFFu, ps[n], off);
            pd[n] += __shfl_xor_sync(0xFFFFFFFFu, pd[n], off);
        }
    }
    if ((cg & 15) == 0) {
        int h = cg >> 4;                      // head id 0..3
        #pragma unroll
        for (int n = 0; n < 8; n++) {
            int gn = n0 + ng * 8 + n;
            if (gn < N_NODES) {
                g_asrc[(size_t)gn * 4 + h] = ps[n];
                g_adst[(size_t)gn * 4 + h] = pd[n];
            }
        }
    }
}

// ---------------- K3a/b/c: prefix scan -> CSR ptr ----------------
__global__ void __launch_bounds__(1024) k_scanA() {
    __shared__ int s[1024];
    int i = blockIdx.x * 1024 + threadIdx.x;
    int v = (i < N_NODES) ? g_deg[i] : 0;
    s[threadIdx.x] = v;
    __syncthreads();
    #pragma unroll
    for (int off = 1; off < 1024; off <<= 1) {
        int u = (threadIdx.x >= off) ? s[threadIdx.x - off] : 0;
        __syncthreads();
        s[threadIdx.x] += u;
        __syncthreads();
    }
    if (i < N_NODES) g_incl[i] = s[threadIdx.x];
    if (threadIdx.x == 1023) g_bsum[blockIdx.x] = s[1023];
}
__global__ void k_scanB() {
    if (threadIdx.x == 0) {
        int run = 0;
        for (int b = 0; b < SCAN_BLOCKS; b++) { g_boff[b] = run; run += g_bsum[b]; }
    }
}
__global__ void __launch_bounds__(1024) k_scanC() {
    int i = blockIdx.x * 1024 + threadIdx.x;
    if (i >= N_NODES) return;
    int incl = g_incl[i] + g_boff[blockIdx.x];
    g_ptr[i] = incl - g_deg[i];
    if (i == N_NODES - 1) g_ptr[N_NODES] = incl;
}

// ------- K4: fill sorted (src, exp) — no atomics -------
__global__ void k_fill(const int* __restrict__ ei) {
    int e = blockIdx.x * blockDim.x + threadIdx.x;
    if (e >= TOT_E) return;
    int s, d;
    if (e < N_EDGES) { s = ei[e]; d = ei[N_EDGES + e]; }
    else             { s = d = e - N_EDGES; }
    int pos = g_ptr[d] + g_rank[e];
    float4 as = *(const float4*)&g_asrc[(size_t)s * 4];
    float4 ad = *(const float4*)&g_adst[(size_t)d * 4];
    float4 ex;
    ex.x = expf(lrelu(as.x + ad.x));
    ex.y = expf(lrelu(as.y + ad.y));
    ex.z = expf(lrelu(as.z + ad.z));
    ex.w = expf(lrelu(as.w + ad.w));
    g_ssrc[pos] = s;
    *(float4*)&g_sexp[(size_t)pos * 4] = ex;
}

// ------- K5: gather-aggregate, warp per node, in-register denominators --
__global__ void __launch_bounds__(256) k_agg(const float* __restrict__ bias,
                                             float* __restrict__ out) {
    int w    = (blockIdx.x * blockDim.x + threadIdx.x) >> 5;   // node id
    int lane = threadIdx.x & 31;
    if (w >= N_NODES) return;
    const int d  = w;
    const int p0 = g_ptr[d];
    const int p1 = g_ptr[d + 1];
    const bool lo = (lane < 16);

    float4 a0 = make_float4(0.f, 0.f, 0.f, 0.f);
    float4 a1 = make_float4(0.f, 0.f, 0.f, 0.f);
    float den0 = 0.f, den1 = 0.f;

    int p = p0;
    for (; p + 4 <= p1; p += 4) {
        int s0 = g_ssrc[p];
        int s1 = g_ssrc[p + 1];
        int s2 = g_ssrc[p + 2];
        int s3 = g_ssrc[p + 3];
        const float4* x0 = (const float4*)&g_xl[(size_t)s0 * HC];
        const float4* x1 = (const float4*)&g_xl[(size_t)s1 * HC];
        const float4* x2 = (const float4*)&g_xl[(size_t)s2 * HC];
        const float4* x3 = (const float4*)&g_xl[(size_t)s3 * HC];
        float4 vA0 = x0[lane], vA1 = x0[lane + 32];
        float4 vB0 = x1[lane], vB1 = x1[lane + 32];
        float4 vC0 = x2[lane], vC1 = x2[lane + 32];
        float4 vD0 = x3[lane], vD1 = x3[lane + 32];
        float4 eA = *(const float4*)&g_sexp[(size_t)p * 4];
        float4 eB = *(const float4*)&g_sexp[(size_t)(p + 1) * 4];
        float4 eC = *(const float4*)&g_sexp[(size_t)(p + 2) * 4];
        float4 eD = *(const float4*)&g_sexp[(size_t)(p + 3) * 4];
        float cA0 = lo ? eA.x : eA.y,  cA1 = lo ? eA.z : eA.w;
        float cB0 = lo ? eB.x : eB.y,  cB1 = lo ? eB.z : eB.w;
        float cC0 = lo ? eC.x : eC.y,  cC1 = lo ? eC.z : eC.w;
        float cD0 = lo ? eD.x : eD.y,  cD1 = lo ? eD.z : eD.w;
        den0 += cA0 + cB0 + cC0 + cD0;
        den1 += cA1 + cB1 + cC1 + cD1;
        a0.x += cA0 * vA0.x; a0.y += cA0 * vA0.y; a0.z += cA0 * vA0.z; a0.w += cA0 * vA0.w;
        a1.x += cA1 * vA1.x; a1.y += cA1 * vA1.y; a1.z += cA1 * vA1.z; a1.w += cA1 * vA1.w;
        a0.x += cB0 * vB0.x; a0.y += cB0 * vB0.y; a0.z += cB0 * vB0.z; a0.w += cB0 * vB0.w;
        a1.x += cB1 * vB1.x; a1.y += cB1 * vB1.y; a1.z += cB1 * vB1.z; a1.w += cB1 * vB1.w;
        a0.x += cC0 * vC0.x; a0.y += cC0 * vC0.y; a0.z += cC0 * vC0.z; a0.w += cC0 * vC0.w;
        a1.x += cC1 * vC1.x; a1.y += cC1 * vC1.y; a1.z += cC1 * vC1.z; a1.w += cC1 * vC1.w;
        a0.x += cD0 * vD0.x; a0.y += cD0 * vD0.y; a0.z += cD0 * vD0.z; a0.w += cD0 * vD0.w;
        a1.x += cD1 * vD1.x; a1.y += cD1 * vD1.y; a1.z += cD1 * vD1.z; a1.w += cD1 * vD1.w;
    }
    for (; p < p1; p++) {
        int    s  = g_ssrc[p];
        float4 ex = *(const float4*)&g_sexp[(size_t)p * 4];
        const float4* xp = (const float4*)&g_xl[(size_t)s * HC];
        float4 v0 = xp[lane], v1 = xp[lane + 32];
        float c0 = lo ? ex.x : ex.y;
        float c1 = lo ? ex.z : ex.w;
        den0 += c0; den1 += c1;
        a0.x += c0 * v0.x; a0.y += c0 * v0.y; a0.z += c0 * v0.z; a0.w += c0 * v0.w;
        a1.x += c1 * v1.x; a1.y += c1 * v1.y; a1.z += c1 * v1.z; a1.w += c1 * v1.w;
    }

    float i0 = 1.f / den0, i1 = 1.f / den1;
    float4 b0 = ((const float4*)bias)[lane];
    float4 b1 = ((const float4*)bias)[lane + 32];
    a0.x = a0.x * i0 + b0.x; a0.y = a0.y * i0 + b0.y;
    a0.z = a0.z * i0 + b0.z; a0.w = a0.w * i0 + b0.w;
    a1.x = a1.x * i1 + b1.x; a1.y = a1.y * i1 + b1.y;
    a1.z = a1.z * i1 + b1.z; a1.w = a1.w * i1 + b1.w;
    a0.x = a0.x > 0.f ? a0.x : expm1f(a0.x);
    a0.y = a0.y > 0.f ? a0.y : expm1f(a0.y);
    a0.z = a0.z > 0.f ? a0.z : expm1f(a0.z);
    a0.w = a0.w > 0.f ? a0.w : expm1f(a0.w);
    a1.x = a1.x > 0.f ? a1.x : expm1f(a1.x);
    a1.y = a1.y > 0.f ? a1.y : expm1f(a1.y);
    a1.z = a1.z > 0.f ? a1.z : expm1f(a1.z);
    a1.w = a1.w > 0.f ? a1.w : expm1f(a1.w);

    float4* op = (float4*)(out + (size_t)d * HC);
    op[lane]      = a0;
    op[lane + 32] = a1;
}

extern "C" void kernel_launch(void* const* d_in, const int* in_sizes, int n_in,
                              void* d_out, int out_size) {
    const float* x    = (const float*)d_in[0];
    const int*   ei   = (const int*)d_in[1];    // int32 (JAX x64 disabled)
    const float* W    = (const float*)d_in[2];
    const float* asrc = (const float*)d_in[3];
    const float* adst = (const float*)d_in[4];
    const float* bias = (const float*)d_in[5];
    float* out = (float*)d_out;

    (void)in_sizes; (void)n_in; (void)out_size;

    // order keeps k_gemm at launch index 3 (the ncu-profiled slot)
    k_wpack<<<(64 * HC + 255) / 256, 256>>>(W);
    k_init<<<(N_NODES + 255) / 256, 256>>>();
    k_hist<<<(TOT_E + 255) / 256, 256>>>(ei);
    k_gemm<<<GEMM_BLOCKS, 256>>>(x, asrc, adst);
    k_scanA<<<SCAN_BLOCKS, 1024>>>();
    k_scanB<<<1, 32>>>();
    k_scanC<<<SCAN_BLOCKS, 1024>>>();
    k_fill<<<(TOT_E + 255) / 256, 256>>>(ei);
    k_agg<<<(N_NODES * 32 + 255) / 256, 256>>>(bias, out);
}